// round 13
// baseline (speedup 1.0000x reference)
#include <cuda_runtime.h>
#include <cuda_bf16.h>
#include <math.h>
#include <stdint.h>

#define TT  8
#define NN  100000
#define HH  128
#define HIN 64

// ---------------- device globals ----------------
__device__ float g_WB[384*HH];       // folded qkv weights [jg][c]
__device__ float g_bias2[TT*384];    // [t][jg]
__device__ float g_pe[TT*HH];
__device__ float g_alpha[1];
__device__ float g_attn[(size_t)TT*NN*HH];

// ---------------- helpers ----------------
__device__ __forceinline__ uint32_t smem_u32(const void* p) {
    uint32_t a;
    asm("{ .reg .u64 t; cvta.to.shared.u64 t, %1; cvt.u32.u64 %0, t; }" : "=r"(a) : "l"(p));
    return a;
}
__device__ __forceinline__ void split_pack(float x, float y, uint32_t& hi, uint32_t& lo) {
    __nv_bfloat16 hx = __float2bfloat16(x);
    __nv_bfloat16 hy = __float2bfloat16(y);
    __nv_bfloat16 lx = __float2bfloat16(x - __bfloat162float(hx));
    __nv_bfloat16 ly = __float2bfloat16(y - __bfloat162float(hy));
    hi = ((uint32_t)__bfloat16_as_ushort(hy) << 16) | (uint32_t)__bfloat16_as_ushort(hx);
    lo = ((uint32_t)__bfloat16_as_ushort(ly) << 16) | (uint32_t)__bfloat16_as_ushort(lx);
}
__device__ __forceinline__ void mma16816(float* d, const uint32_t* a, const uint32_t* b) {
    asm volatile(
        "mma.sync.aligned.m16n8k16.row.col.f32.bf16.bf16.f32 "
        "{%0,%1,%2,%3}, {%4,%5,%6,%7}, {%8,%9}, {%0,%1,%2,%3};"
        : "+f"(d[0]), "+f"(d[1]), "+f"(d[2]), "+f"(d[3])
        : "r"(a[0]), "r"(a[1]), "r"(a[2]), "r"(a[3]), "r"(b[0]), "r"(b[1]));
}
__device__ __forceinline__ void ldsm_x4(uint32_t* r, uint32_t addr) {
    asm volatile("ldmatrix.sync.aligned.m8n8.x4.shared.b16 {%0,%1,%2,%3}, [%4];"
        : "=r"(r[0]), "=r"(r[1]), "=r"(r[2]), "=r"(r[3]) : "r"(addr));
}
__device__ __forceinline__ void ldsm_x2(uint32_t* r, uint32_t addr) {
    asm volatile("ldmatrix.sync.aligned.m8n8.x2.shared.b16 {%0,%1}, [%2];"
        : "=r"(r[0]), "=r"(r[1]) : "r"(addr));
}

// ---------------- prep1: PE + alpha ----------------
__global__ void prep1_kernel(const float* __restrict__ res_alpha) {
    int i = blockIdx.x * blockDim.x + threadIdx.x;
    if (i < TT*HH) {
        int t = i >> 7, m = i & 127;
        double div = exp((double)(m & ~1) * (-log(100000.0)) / 128.0);
        double phv = (double)(t + 1) * div;
        g_pe[i] = (float)((m & 1) ? cos(phv) : sin(phv));
    }
    if (i == 0) g_alpha[0] = 1.0f / (1.0f + expf(-res_alpha[0]));
}

// ---------------- prep2: fold proj into qkv (fp32) ----------------
__global__ void prep2_kernel(const float* __restrict__ proj_w, const float* __restrict__ proj_b,
                             const float* __restrict__ q_w, const float* __restrict__ k_w,
                             const float* __restrict__ v_w)
{
    int idx = blockIdx.x * blockDim.x + threadIdx.x;
    const int NW = 384*HH;
    const int NB = NW + TT*384;
    if (idx < NW) {
        int j = idx / HH, c = idx % HH;
        int mat = j >> 7, jj = j & 127;
        const float* w = (mat==0) ? q_w : ((mat==1) ? k_w : v_w);
        float s = 0.f;
        for (int m = 0; m < HH; m++) s += w[jj*HH+m] * proj_w[m*HH+c];
        g_WB[idx] = s;
    } else if (idx < NB) {
        int r = idx - NW;
        int t = r / 384, j = r % 384;
        int mat = j >> 7, jj = j & 127;
        const float* w = (mat==0) ? q_w : ((mat==1) ? k_w : v_w);
        float s = 0.f;
        for (int m = 0; m < HH; m++) s += (proj_b[m] + g_pe[t*HH+m]) * w[jj*HH+m];
        g_bias2[r] = s;
    }
}

// ---------------- attn kernel: M=48 tile (6 nodes), single A buffer ----------------
// smem: Blo 104448 | Ahi 13056 | Alo 13056 | C 48*388*4=74496 | bias 12288 => 217344
#define SA_BLO   0
#define SA_AHI   104448
#define SA_ALO   117504
#define SA_C     130560
#define SA_BIAS  205056
#define SA_TOTAL 217344
#define CST      388
#define MROWS    48
#define NODES_T  6

__global__ __launch_bounds__(256, 1) void attn_mma_kernel(const float* __restrict__ inter)
{
    extern __shared__ char smc[];
    uint32_t smb = smem_u32(smc);
    uint32_t* Blo = (uint32_t*)(smc + SA_BLO);   // [384][68]
    uint32_t* Ahi = (uint32_t*)(smc + SA_AHI);   // [48][68]
    uint32_t* Alo = (uint32_t*)(smc + SA_ALO);
    float*    C   = (float*)(smc + SA_C);        // [48][388]
    float*  sbias = (float*)(smc + SA_BIAS);     // [8][384]

    int tid = threadIdx.x, warp = tid >> 5, lane = tid & 31;
    int g = lane >> 2, tc = lane & 3;
    int n0 = warp * 48;                // 8 warps x 48 cols = 384

    // stage B-lo + bias (once)
    for (int i = tid; i < 384*64; i += 256) {
        int n = i >> 6, cp = i & 63;
        float2 w = *(const float2*)(g_WB + n*128 + cp*2);
        uint32_t h, l; split_pack(w.x, w.y, h, l);
        Blo[n*68 + cp] = l;
    }
    for (int i = tid; i < TT*384; i += 256) sbias[i] = g_bias2[i];

    // per-warp B-hi fragments in registers (once)
    uint32_t bh[6][8][2];
    #pragma unroll
    for (int nn = 0; nn < 6; nn++) {
        #pragma unroll
        for (int kk = 0; kk < 8; kk++) {
            int n = n0 + nn*8 + g;
            int k = kk*16 + tc*2;
            float2 w0 = *(const float2*)(g_WB + n*128 + k);
            float2 w1 = *(const float2*)(g_WB + n*128 + k + 8);
            uint32_t h, l;
            split_pack(w0.x, w0.y, h, l); bh[nn][kk][0] = h;
            split_pack(w1.x, w1.y, h, l); bh[nn][kk][1] = h;
        }
    }

    uint32_t bBase[6];
    #pragma unroll
    for (int nn = 0; nn < 6; nn++)
        bBase[nn] = smb + SA_BLO + (uint32_t)(n0 + nn*8 + (lane & 7))*272 + (uint32_t)((lane >> 3) & 1)*16;

    const int nTiles = (NN + NODES_T - 1) / NODES_T;   // 16667

    // ---- prologue: stage first tile ----
    {
        int tile0 = blockIdx.x;
        for (int i = tid; i < MROWS*64; i += 256) {
            int row = i >> 6, cp = i & 63;
            int t = row & 7;
            int node = tile0*NODES_T + (row >> 3);
            if (node >= NN) node = NN - 1;
            float2 a = *(const float2*)(inter + ((size_t)t*NN + (size_t)node)*HH + cp*2);
            uint32_t h, l; split_pack(a.x, a.y, h, l);
            Ahi[row*68 + cp] = h;
            Alo[row*68 + cp] = l;
        }
    }
    __syncthreads();

    uint32_t aBaseHi = smb + SA_AHI + (uint32_t)(lane & 15)*272 + (uint32_t)(lane >> 4)*16;
    uint32_t aBaseLo = aBaseHi + (SA_ALO - SA_AHI);

    for (int tile = blockIdx.x; tile < nTiles; tile += gridDim.x) {
        // ---- prefetch next tile's A into registers ----
        int ptile = tile + gridDim.x;
        bool havepf = ptile < nTiles;
        float2 pf[12];
        if (havepf) {
            #pragma unroll
            for (int j = 0; j < 12; j++) {
                int i = tid + j*256;
                int row = i >> 6, cp = i & 63;
                int t = row & 7;
                int node = ptile*NODES_T + (row >> 3);
                if (node >= NN) node = NN - 1;
                pf[j] = *(const float2*)(inter + ((size_t)t*NN + (size_t)node)*HH + cp*2);
            }
        }

        // ---- MMA: C[48][384] = A x W ; two pass-major sweeps (mm{0,1}, mm{2}) ----
        #pragma unroll
        for (int sw = 0; sw < 2; sw++) {
            const int mm0 = sw * 2;
            const int nm  = sw ? 1 : 2;
            float acc[2][6][4];
            #pragma unroll
            for (int m = 0; m < 2; m++)
                #pragma unroll
                for (int nn = 0; nn < 6; nn++) {
                    acc[m][nn][0] = 0.f; acc[m][nn][1] = 0.f;
                    acc[m][nn][2] = 0.f; acc[m][nn][3] = 0.f;
                }
            #pragma unroll
            for (int kh = 0; kh < 2; kh++) {
                #pragma unroll
                for (int q = 0; q < 4; q++) {
                    int kk = kh*4 + q;
                    uint32_t bl[6][2];
                    #pragma unroll
                    for (int nn = 0; nn < 6; nn++)
                        ldsm_x2(bl[nn], bBase[nn] + kk*32);
                    uint32_t ah[2][4], al[2][4];
                    #pragma unroll
                    for (int m = 0; m < nm; m++) {
                        ldsm_x4(ah[m], aBaseHi + (uint32_t)(mm0+m)*4352 + kh*128 + q*32);
                        ldsm_x4(al[m], aBaseLo + (uint32_t)(mm0+m)*4352 + kh*128 + q*32);
                    }
                    #pragma unroll
                    for (int m = 0; m < nm; m++)
                        #pragma unroll
                        for (int nn = 0; nn < 6; nn++)
                            mma16816(acc[m][nn], ah[m], bh[nn][kk]);
                    #pragma unroll
                    for (int m = 0; m < nm; m++)
                        #pragma unroll
                        for (int nn = 0; nn < 6; nn++)
                            mma16816(acc[m][nn], ah[m], bl[nn]);
                    #pragma unroll
                    for (int m = 0; m < nm; m++)
                        #pragma unroll
                        for (int nn = 0; nn < 6; nn++)
                            mma16816(acc[m][nn], al[m], bh[nn][kk]);
                }
            }
            #pragma unroll
            for (int m = 0; m < nm; m++) {
                #pragma unroll
                for (int nn = 0; nn < 6; nn++) {
                    int j = n0 + nn*8 + tc*2;
                    float2 b = *(const float2*)(sbias + g*384 + j);
                    int rlo = (mm0+m)*16 + g, rhi = rlo + 8;
                    *(float2*)(C + rlo*CST + j) = make_float2(acc[m][nn][0]+b.x, acc[m][nn][1]+b.y);
                    *(float2*)(C + rhi*CST + j) = make_float2(acc[m][nn][2]+b.x, acc[m][nn][3]+b.y);
                }
            }
        }
        __syncthreads();   // C visible; A fully consumed

        // ---- epilogue: 48 (node,t) tasks, 6 per warp; k/v cached per node ----
        {
            int prev_nl = -1;
            float kreg[8][4], vreg[8][4];
            #pragma unroll
            for (int ti = 0; ti < 6; ti++) {
                int task = warp*6 + ti;
                int nl = task >> 3, t = task & 7;
                const float* Cn = C + nl*8*CST;
                if (nl != prev_nl) {
                    #pragma unroll
                    for (int s = 0; s < 8; s++)
                        #pragma unroll
                        for (int u = 0; u < 4; u++) {
                            kreg[s][u] = Cn[s*CST + 128 + lane + 32*u];
                            vreg[s][u] = Cn[s*CST + 256 + lane + 32*u];
                        }
                    prev_nl = nl;
                }
                float qv[4];
                #pragma unroll
                for (int u = 0; u < 4; u++) qv[u] = Cn[t*CST + lane + 32*u];
                float sc[8];
                #pragma unroll
                for (int s = 0; s < 8; s++) {
                    float p = qv[0]*kreg[s][0] + qv[1]*kreg[s][1]
                            + qv[2]*kreg[s][2] + qv[3]*kreg[s][3];
                    #pragma unroll
                    for (int o = 16; o > 0; o >>= 1) p += __shfl_xor_sync(0xffffffffu, p, o);
                    sc[s] = p;
                }
                float mx = sc[0];
                #pragma unroll
                for (int s = 1; s < 8; s++) mx = fmaxf(mx, sc[s]);
                float sum = 0.f;
                #pragma unroll
                for (int s = 0; s < 8; s++) { sc[s] = expf(sc[s] - mx); sum += sc[s]; }
                float inv = 1.f / sum;
                float of[4] = {0.f, 0.f, 0.f, 0.f};
                #pragma unroll
                for (int s = 0; s < 8; s++) {
                    float w = sc[s] * inv;
                    #pragma unroll
                    for (int u = 0; u < 4; u++) of[u] += w * vreg[s][u];
                }
                int node_g = tile*NODES_T + nl;
                if (node_g < NN) {
                    #pragma unroll
                    for (int u = 0; u < 4; u++)
                        g_attn[((size_t)t*NN + (size_t)node_g)*HH + lane + 32*u] = of[u];
                }
            }
        }

        // ---- commit prefetched A (A dead since post-MMA barrier) ----
        if (havepf) {
            #pragma unroll
            for (int j = 0; j < 12; j++) {
                int i = tid + j*256;
                int row = i >> 6, cp = i & 63;
                uint32_t h, l; split_pack(pf[j].x, pf[j].y, h, l);
                Ahi[row*68 + cp] = h;
                Alo[row*68 + cp] = l;
            }
        }
        __syncthreads();   // A[next] staged; C reads done
    }
}

// ---------------- out kernel: M=32, 2 CTAs/SM, HMMA fc+res + gate + LN ----------------
// smem: fcBlo 34816 | resBlo 18432 | Ahi 8704 | Alo 8704 | Xhi 4608 | Xlo 4608
//       C 32*132*4=16896 | par 2064  => 98832 (2 CTAs/SM)
#define SO_FCBLO  0
#define SO_RESBLO 34816
#define SO_AHI    53248
#define SO_ALO    61952
#define SO_XHI    70656
#define SO_XLO    75264
#define SO_C      79872
#define SO_PAR    96768
#define SO_TOTAL  98832

__global__ __launch_bounds__(256, 2) void out_mma_kernel(const float* __restrict__ x,
        const float* __restrict__ fc_w, const float* __restrict__ fc_b,
        const float* __restrict__ res_w, const float* __restrict__ res_b,
        const float* __restrict__ ln_g, const float* __restrict__ ln_b,
        float* __restrict__ out)
{
    extern __shared__ char smc[];
    uint32_t smb = smem_u32(smc);
    uint32_t* fBlo = (uint32_t*)(smc + SO_FCBLO);
    uint32_t* rBlo = (uint32_t*)(smc + SO_RESBLO);
    uint32_t* Ahi  = (uint32_t*)(smc + SO_AHI);
    uint32_t* Alo  = (uint32_t*)(smc + SO_ALO);
    uint32_t* Xhi  = (uint32_t*)(smc + SO_XHI);
    uint32_t* Xlo  = (uint32_t*)(smc + SO_XLO);
    float*    C    = (float*)(smc + SO_C);
    float*    par  = (float*)(smc + SO_PAR);

    int tid = threadIdx.x, warp = tid >> 5, lane = tid & 31;
    int g = lane >> 2, tc = lane & 3;
    int n0 = warp * 16;

    for (int i = tid; i < 128*64; i += 256) {
        int n = i >> 6, cp = i & 63;
        float2 w = *(const float2*)(fc_w + n*128 + cp*2);
        uint32_t h, l; split_pack(w.x, w.y, h, l);
        fBlo[n*68 + cp] = l;
    }
    for (int i = tid; i < 128*32; i += 256) {
        int n = i >> 5, cp = i & 31;
        float2 w = *(const float2*)(res_w + n*64 + cp*2);
        uint32_t h, l; split_pack(w.x, w.y, h, l);
        rBlo[n*36 + cp] = l;
    }
    if (tid < 128) {
        par[tid] = fc_b[tid]; par[128+tid] = res_b[tid];
        par[256+tid] = ln_g[tid]; par[384+tid] = ln_b[tid];
    }
    if (tid == 0) par[512] = g_alpha[0];

    uint32_t bf[2][8][2], br[2][4][2];
    #pragma unroll
    for (int nn = 0; nn < 2; nn++) {
        int n = n0 + nn*8 + g;
        #pragma unroll
        for (int kk = 0; kk < 8; kk++) {
            int k = kk*16 + tc*2;
            float2 w0 = *(const float2*)(fc_w + n*128 + k);
            float2 w1 = *(const float2*)(fc_w + n*128 + k + 8);
            uint32_t h, l;
            split_pack(w0.x, w0.y, h, l); bf[nn][kk][0] = h;
            split_pack(w1.x, w1.y, h, l); bf[nn][kk][1] = h;
        }
        #pragma unroll
        for (int kk = 0; kk < 4; kk++) {
            int k = kk*16 + tc*2;
            float2 w0 = *(const float2*)(res_w + n*64 + k);
            float2 w1 = *(const float2*)(res_w + n*64 + k + 8);
            uint32_t h, l;
            split_pack(w0.x, w0.y, h, l); br[nn][kk][0] = h;
            split_pack(w1.x, w1.y, h, l); br[nn][kk][1] = h;
        }
    }
    __syncthreads();
    float alpha = par[512];
    float beta  = 1.f - alpha;

    uint32_t aBaseHi = smb + SO_AHI + (uint32_t)(lane & 15)*272 + (uint32_t)(lane >> 4)*16;
    uint32_t aBaseLo = aBaseHi + (SO_ALO - SO_AHI);
    uint32_t xBaseHi = smb + SO_XHI + (uint32_t)(lane & 15)*144 + (uint32_t)(lane >> 4)*16;
    uint32_t xBaseLo = xBaseHi + (SO_XLO - SO_XHI);
    uint32_t bfBase[2], brBase[2];
    #pragma unroll
    for (int nn = 0; nn < 2; nn++) {
        bfBase[nn] = smb + SO_FCBLO  + (uint32_t)(n0 + nn*8 + (lane & 7))*272 + (uint32_t)((lane >> 3) & 1)*16;
        brBase[nn] = smb + SO_RESBLO + (uint32_t)(n0 + nn*8 + (lane & 7))*144 + (uint32_t)((lane >> 3) & 1)*16;
    }

    const int nTiles = (TT*NN)/32;   // 25000
    for (int tile = blockIdx.x; tile < nTiles; tile += gridDim.x) {
        size_t r0 = (size_t)tile * 32;
        for (int i = tid; i < 2048; i += 256) {
            int row = i >> 6, cp = i & 63;
            float2 a = *(const float2*)(g_attn + (r0 + row)*HH + cp*2);
            uint32_t h, l; split_pack(a.x, a.y, h, l);
            Ahi[row*68 + cp] = h; Alo[row*68 + cp] = l;
        }
        for (int i = tid; i < 1024; i += 256) {
            int row = i >> 5, cp = i & 31;
            float2 a = *(const float2*)(x + (r0 + row)*HIN + cp*2);
            uint32_t h, l; split_pack(a.x, a.y, h, l);
            Xhi[row*36 + cp] = h; Xlo[row*36 + cp] = l;
        }
        __syncthreads();

        #pragma unroll
        for (int mm = 0; mm < 2; mm++) {
            float accf[2][4];
            #pragma unroll
            for (int nn = 0; nn < 2; nn++) { accf[nn][0]=0.f; accf[nn][1]=0.f; accf[nn][2]=0.f; accf[nn][3]=0.f; }
            float accr[2][4];
            #pragma unroll
            for (int nn = 0; nn < 2; nn++) { accr[nn][0]=0.f; accr[nn][1]=0.f; accr[nn][2]=0.f; accr[nn][3]=0.f; }
            uint32_t aH = aBaseHi + (uint32_t)mm*4352;
            uint32_t aL = aBaseLo + (uint32_t)mm*4352;
            #pragma unroll
            for (int kh = 0; kh < 2; kh++) {
                #pragma unroll
                for (int q = 0; q < 4; q++) {
                    int kk = kh*4 + q;
                    uint32_t blf[2][2];
                    #pragma unroll
                    for (int nn = 0; nn < 2; nn++) ldsm_x2(blf[nn], bfBase[nn] + kk*32);
                    uint32_t ah[4], al[4];
                    ldsm_x4(ah, aH + kh*128 + q*32);
                    ldsm_x4(al, aL + kh*128 + q*32);
                    #pragma unroll
                    for (int nn = 0; nn < 2; nn++) mma16816(accf[nn], ah, bf[nn][kk]);
                    #pragma unroll
                    for (int nn = 0; nn < 2; nn++) mma16816(accf[nn], ah, blf[nn]);
                    #pragma unroll
                    for (int nn = 0; nn < 2; nn++) mma16816(accf[nn], al, bf[nn][kk]);
                }
            }
            {
                uint32_t xH = xBaseHi + (uint32_t)mm*2304;
                uint32_t xL = xBaseLo + (uint32_t)mm*2304;
                #pragma unroll
                for (int kk = 0; kk < 4; kk++) {
                    uint32_t blr[2][2];
                    #pragma unroll
                    for (int nn = 0; nn < 2; nn++) ldsm_x2(blr[nn], brBase[nn] + kk*32);
                    uint32_t ah[4], al[4];
                    ldsm_x4(ah, xH + kk*32);
                    ldsm_x4(al, xL + kk*32);
                    #pragma unroll
                    for (int nn = 0; nn < 2; nn++) mma16816(accr[nn], ah, br[nn][kk]);
                    #pragma unroll
                    for (int nn = 0; nn < 2; nn++) mma16816(accr[nn], ah, blr[nn]);
                    #pragma unroll
                    for (int nn = 0; nn < 2; nn++) mma16816(accr[nn], al, br[nn][kk]);
                }
            }
            #pragma unroll
            for (int nn = 0; nn < 2; nn++) {
                int j = n0 + nn*8 + tc*2;
                float2 fb = *(const float2*)(par + j);
                float2 rb = *(const float2*)(par + 128 + j);
                int rlo = mm*16 + g, rhi = rlo + 8;
                float v0 = fmaxf(accf[nn][0]+fb.x, 0.f)*alpha + (accr[nn][0]+rb.x)*beta;
                float v1 = fmaxf(accf[nn][1]+fb.y, 0.f)*alpha + (accr[nn][1]+rb.y)*beta;
                float v2 = fmaxf(accf[nn][2]+fb.x, 0.f)*alpha + (accr[nn][2]+rb.x)*beta;
                float v3 = fmaxf(accf[nn][3]+fb.y, 0.f)*alpha + (accr[nn][3]+rb.y)*beta;
                *(float2*)(C + rlo*132 + j) = make_float2(v0, v1);
                *(float2*)(C + rhi*132 + j) = make_float2(v2, v3);
            }
        }
        __syncthreads();

        #pragma unroll
        for (int r8 = 0; r8 < 4; r8++) {
            int r = warp*4 + r8;
            float o[4];
            float s = 0.f, s2 = 0.f;
            #pragma unroll
            for (int u = 0; u < 4; u++) {
                o[u] = C[r*132 + lane + 32*u];
                s += o[u]; s2 += o[u]*o[u];
            }
            #pragma unroll
            for (int off = 16; off > 0; off >>= 1) {
                s  += __shfl_xor_sync(0xffffffffu, s,  off);
                s2 += __shfl_xor_sync(0xffffffffu, s2, off);
            }
            float mean = s * (1.f/HH);
            float var  = s2 * (1.f/HH) - mean*mean;
            float inv  = rsqrtf(var + 1e-5f);
            #pragma unroll
            for (int u = 0; u < 4; u++) {
                int col = lane + 32*u;
                out[(r0 + r)*HH + col] = (o[u]-mean)*inv*par[256+col] + par[384+col];
            }
        }
        __syncthreads();
    }
}

// ---------------- launch ----------------
extern "C" void kernel_launch(void* const* d_in, const int* in_sizes, int n_in,
                              void* d_out, int out_size)
{
    const float* inter     = (const float*)d_in[0];
    const float* x         = (const float*)d_in[1];
    const float* proj_w    = (const float*)d_in[2];
    const float* proj_b    = (const float*)d_in[3];
    const float* q_w       = (const float*)d_in[4];
    const float* k_w       = (const float*)d_in[5];
    const float* v_w       = (const float*)d_in[6];
    const float* fc_w      = (const float*)d_in[7];
    const float* fc_b      = (const float*)d_in[8];
    const float* res_w     = (const float*)d_in[9];
    const float* res_b     = (const float*)d_in[10];
    const float* res_alpha = (const float*)d_in[11];
    const float* ln_g      = (const float*)d_in[12];
    const float* ln_b      = (const float*)d_in[13];
    float* out = (float*)d_out;

    cudaFuncSetAttribute(attn_mma_kernel, cudaFuncAttributeMaxDynamicSharedMemorySize, SA_TOTAL);
    cudaFuncSetAttribute(out_mma_kernel,  cudaFuncAttributeMaxDynamicSharedMemorySize, SO_TOTAL);

    prep1_kernel<<<4, 256>>>(res_alpha);
    prep2_kernel<<<205, 256>>>(proj_w, proj_b, q_w, k_w, v_w);
    attn_mma_kernel<<<148, 256, SA_TOTAL>>>(inter);
    out_mma_kernel<<<296, 256, SO_TOTAL>>>(x, fc_w, fc_b, res_w, res_b, ln_g, ln_b, out);
}

// round 14
// speedup vs baseline: 1.1476x; 1.1476x over previous
#include <cuda_runtime.h>
#include <cuda_bf16.h>
#include <math.h>
#include <stdint.h>

#define TT  8
#define NN  100000
#define HH  128
#define HIN 64

// ---------------- device globals ----------------
__device__ float g_WB[384*HH];       // folded qkv weights [jg][c]
__device__ float g_bias2[TT*384];    // [t][jg]
__device__ float g_pe[TT*HH];
__device__ float g_alpha[1];
__device__ uint32_t g_attnH[(size_t)TT*NN*64];   // attn out, packed bf16-hi pairs
__device__ uint32_t g_attnL[(size_t)TT*NN*64];   // attn out, packed bf16-lo pairs

// ---------------- helpers ----------------
__device__ __forceinline__ uint32_t smem_u32(const void* p) {
    uint32_t a;
    asm("{ .reg .u64 t; cvta.to.shared.u64 t, %1; cvt.u32.u64 %0, t; }" : "=r"(a) : "l"(p));
    return a;
}
__device__ __forceinline__ void split_pack(float x, float y, uint32_t& hi, uint32_t& lo) {
    __nv_bfloat16 hx = __float2bfloat16(x);
    __nv_bfloat16 hy = __float2bfloat16(y);
    __nv_bfloat16 lx = __float2bfloat16(x - __bfloat162float(hx));
    __nv_bfloat16 ly = __float2bfloat16(y - __bfloat162float(hy));
    hi = ((uint32_t)__bfloat16_as_ushort(hy) << 16) | (uint32_t)__bfloat16_as_ushort(hx);
    lo = ((uint32_t)__bfloat16_as_ushort(ly) << 16) | (uint32_t)__bfloat16_as_ushort(lx);
}
__device__ __forceinline__ void mma16816(float* d, const uint32_t* a, const uint32_t* b) {
    asm volatile(
        "mma.sync.aligned.m16n8k16.row.col.f32.bf16.bf16.f32 "
        "{%0,%1,%2,%3}, {%4,%5,%6,%7}, {%8,%9}, {%0,%1,%2,%3};"
        : "+f"(d[0]), "+f"(d[1]), "+f"(d[2]), "+f"(d[3])
        : "r"(a[0]), "r"(a[1]), "r"(a[2]), "r"(a[3]), "r"(b[0]), "r"(b[1]));
}
__device__ __forceinline__ void ldsm_x4(uint32_t* r, uint32_t addr) {
    asm volatile("ldmatrix.sync.aligned.m8n8.x4.shared.b16 {%0,%1,%2,%3}, [%4];"
        : "=r"(r[0]), "=r"(r[1]), "=r"(r[2]), "=r"(r[3]) : "r"(addr));
}
__device__ __forceinline__ void ldsm_x2(uint32_t* r, uint32_t addr) {
    asm volatile("ldmatrix.sync.aligned.m8n8.x2.shared.b16 {%0,%1}, [%2];"
        : "=r"(r[0]), "=r"(r[1]) : "r"(addr));
}
#define CP16(dst, src) \
    asm volatile("cp.async.cg.shared.global [%0], [%1], 16;" :: "r"(dst), "l"(src) : "memory")
#define CP_COMMIT() asm volatile("cp.async.commit_group;" ::: "memory")
#define CP_WAIT0()  asm volatile("cp.async.wait_group 0;" ::: "memory")

// ---------------- prep1: PE + alpha ----------------
__global__ void prep1_kernel(const float* __restrict__ res_alpha) {
    int i = blockIdx.x * blockDim.x + threadIdx.x;
    if (i < TT*HH) {
        int t = i >> 7, m = i & 127;
        double div = exp((double)(m & ~1) * (-log(100000.0)) / 128.0);
        double phv = (double)(t + 1) * div;
        g_pe[i] = (float)((m & 1) ? cos(phv) : sin(phv));
    }
    if (i == 0) g_alpha[0] = 1.0f / (1.0f + expf(-res_alpha[0]));
}

// ---------------- prep2: fold proj into qkv (fp32) ----------------
__global__ void prep2_kernel(const float* __restrict__ proj_w, const float* __restrict__ proj_b,
                             const float* __restrict__ q_w, const float* __restrict__ k_w,
                             const float* __restrict__ v_w)
{
    int idx = blockIdx.x * blockDim.x + threadIdx.x;
    const int NW = 384*HH;
    const int NB = NW + TT*384;
    if (idx < NW) {
        int j = idx / HH, c = idx % HH;
        int mat = j >> 7, jj = j & 127;
        const float* w = (mat==0) ? q_w : ((mat==1) ? k_w : v_w);
        float s = 0.f;
        for (int m = 0; m < HH; m++) s += w[jj*HH+m] * proj_w[m*HH+c];
        g_WB[idx] = s;
    } else if (idx < NB) {
        int r = idx - NW;
        int t = r / 384, j = r % 384;
        int mat = j >> 7, jj = j & 127;
        const float* w = (mat==0) ? q_w : ((mat==1) ? k_w : v_w);
        float s = 0.f;
        for (int m = 0; m < HH; m++) s += (proj_b[m] + g_pe[t*HH+m]) * w[jj*HH+m];
        g_bias2[r] = s;
    }
}

// ---------------- attn kernel: HMMA qkv + double-buffered A prefetch ----------------
// M=32 tile (4 nodes), 256 threads.
// smem: Blo 104448 | A buf0 hi/lo 8704+8704 | A buf1 hi/lo 8704+8704
//       C 32*388*4=49664 | bias 12288  => 201216
#define SA_BLO   0
#define SA_AHI   104448
#define SA_ALO   113152
#define ABUF     17408
#define SA_C     139264
#define SA_BIAS  188928
#define SA_TOTAL 201216
#define CST      388

__global__ __launch_bounds__(256, 1) void attn_mma_kernel(const float* __restrict__ inter)
{
    extern __shared__ char smc[];
    uint32_t smb = smem_u32(smc);
    uint32_t* Blo = (uint32_t*)(smc + SA_BLO);   // [384][68] packed bf16-lo pairs
    float*    C   = (float*)(smc + SA_C);        // [32][388]
    float*  sbias = (float*)(smc + SA_BIAS);     // [8][384]

    int tid = threadIdx.x, warp = tid >> 5, lane = tid & 31;
    int g = lane >> 2, tc = lane & 3;
    int n0 = warp * 48;                // 8 warps x 48 cols = 384

    // stage B-lo + bias (once)
    for (int i = tid; i < 384*64; i += 256) {
        int n = i >> 6, cp = i & 63;
        float2 w = *(const float2*)(g_WB + n*128 + cp*2);
        uint32_t h, l; split_pack(w.x, w.y, h, l);
        Blo[n*68 + cp] = l;
    }
    for (int i = tid; i < TT*384; i += 256) sbias[i] = g_bias2[i];

    // per-warp B-hi fragments in registers (once)
    uint32_t bh[6][8][2];
    #pragma unroll
    for (int nn = 0; nn < 6; nn++) {
        #pragma unroll
        for (int kk = 0; kk < 8; kk++) {
            int n = n0 + nn*8 + g;
            int k = kk*16 + tc*2;
            float2 w0 = *(const float2*)(g_WB + n*128 + k);
            float2 w1 = *(const float2*)(g_WB + n*128 + k + 8);
            uint32_t h, l;
            split_pack(w0.x, w0.y, h, l); bh[nn][kk][0] = h;
            split_pack(w1.x, w1.y, h, l); bh[nn][kk][1] = h;
        }
    }

    uint32_t bBase[6];
    #pragma unroll
    for (int nn = 0; nn < 6; nn++)
        bBase[nn] = smb + SA_BLO + (uint32_t)(n0 + nn*8 + (lane & 7))*272 + (uint32_t)((lane >> 3) & 1)*16;

    int epi_node = warp >> 1;          // warp's node for epilogue
    int epi_th   = (warp & 1) * 4;     // t offset
    const int nTiles = NN/4;

    // ---- prologue: stage first tile into buffer 0 ----
    {
        int tile0 = blockIdx.x;
        uint32_t* Ahi = (uint32_t*)(smc + SA_AHI);
        uint32_t* Alo = (uint32_t*)(smc + SA_ALO);
        for (int i = tid; i < 2048; i += 256) {
            int row = i >> 6, cp = i & 63;
            int t = row & 7, nl = row >> 3;
            float2 a = *(const float2*)(inter + ((size_t)t*NN + (size_t)(tile0*4 + nl))*HH + cp*2);
            uint32_t h, l; split_pack(a.x, a.y, h, l);
            Ahi[row*68 + cp] = h;
            Alo[row*68 + cp] = l;
        }
    }
    __syncthreads();

    int cur = 0;
    for (int tile = blockIdx.x; tile < nTiles; tile += gridDim.x) {
        // ---- prefetch next tile's A into registers ----
        int ptile = tile + gridDim.x;
        bool havepf = ptile < nTiles;
        float2 pf[8];
        if (havepf) {
            #pragma unroll
            for (int j = 0; j < 8; j++) {
                int i = tid + j*256;
                int row = i >> 6, cp = i & 63;
                int t = row & 7, nl = row >> 3;
                pf[j] = *(const float2*)(inter + ((size_t)t*NN + (size_t)(ptile*4 + nl))*HH + cp*2);
            }
        }

        // ---- MMA: C[32][384] = A x W, 3 precision passes ----
        uint32_t aBaseHi = smb + SA_AHI + (uint32_t)cur*ABUF
                         + (uint32_t)(lane & 15)*272 + (uint32_t)(lane >> 4)*16;
        uint32_t aBaseLo = aBaseHi + 8704;
        #pragma unroll
        for (int mm = 0; mm < 2; mm++) {
            float acc[6][4];
            #pragma unroll
            for (int nn = 0; nn < 6; nn++) {
                acc[nn][0] = 0.f; acc[nn][1] = 0.f; acc[nn][2] = 0.f; acc[nn][3] = 0.f;
            }
            uint32_t aH = aBaseHi + (uint32_t)mm*4352;   // 16 rows * 272B
            uint32_t aL = aBaseLo + (uint32_t)mm*4352;
            #pragma unroll
            for (int kh = 0; kh < 2; kh++) {
                uint32_t ah[4][4], al[4][4];
                #pragma unroll
                for (int q = 0; q < 4; q++) {
                    ldsm_x4(ah[q], aH + kh*128 + q*32);
                    ldsm_x4(al[q], aL + kh*128 + q*32);
                }
                #pragma unroll
                for (int nn = 0; nn < 6; nn++) {
                    #pragma unroll
                    for (int q = 0; q < 4; q++) {
                        int kk = kh*4 + q;
                        uint32_t bl[2];
                        ldsm_x2(bl, bBase[nn] + kk*32);
                        mma16816(acc[nn], ah[q], bh[nn][kk]);
                        mma16816(acc[nn], ah[q], bl);
                        mma16816(acc[nn], al[q], bh[nn][kk]);
                    }
                }
            }
            // write C with bias (t index of rows mm*16+g and +8 is g)
            #pragma unroll
            for (int nn = 0; nn < 6; nn++) {
                int j = n0 + nn*8 + tc*2;
                float2 b = *(const float2*)(sbias + g*384 + j);
                int rlo = mm*16 + g, rhi = rlo + 8;
                *(float2*)(C + rlo*CST + j) = make_float2(acc[nn][0]+b.x, acc[nn][1]+b.y);
                *(float2*)(C + rhi*CST + j) = make_float2(acc[nn][2]+b.x, acc[nn][3]+b.y);
            }
        }
        __syncthreads();   // C visible; A[cur] fully consumed

        // ---- epilogue: warp owns (node, 4 t's); writes pre-split hi/lo planes ----
        {
            const float* Cn = C + epi_node*8*CST;
            float kreg[8][4], vreg[8][4];
            #pragma unroll
            for (int s = 0; s < 8; s++) {
                #pragma unroll
                for (int u = 0; u < 4; u++) {
                    kreg[s][u] = Cn[s*CST + 128 + lane + 32*u];
                    vreg[s][u] = Cn[s*CST + 256 + lane + 32*u];
                }
            }
            size_t node_g = (size_t)(tile*4 + epi_node);
            #pragma unroll
            for (int tt = 0; tt < 4; tt++) {
                int t = epi_th + tt;
                float qv[4];
                #pragma unroll
                for (int u = 0; u < 4; u++) qv[u] = Cn[t*CST + lane + 32*u];
                float sc[8];
                #pragma unroll
                for (int s = 0; s < 8; s++) {
                    float p = qv[0]*kreg[s][0] + qv[1]*kreg[s][1]
                            + qv[2]*kreg[s][2] + qv[3]*kreg[s][3];
                    #pragma unroll
                    for (int o = 16; o > 0; o >>= 1) p += __shfl_xor_sync(0xffffffffu, p, o);
                    sc[s] = p;
                }
                float mx = sc[0];
                #pragma unroll
                for (int s = 1; s < 8; s++) mx = fmaxf(mx, sc[s]);
                float sum = 0.f;
                #pragma unroll
                for (int s = 0; s < 8; s++) { sc[s] = expf(sc[s] - mx); sum += sc[s]; }
                float inv = 1.f / sum;
                float of[4] = {0.f, 0.f, 0.f, 0.f};
                #pragma unroll
                for (int s = 0; s < 8; s++) {
                    float w = sc[s] * inv;
                    #pragma unroll
                    for (int u = 0; u < 4; u++) of[u] += w * vreg[s][u];
                }
                size_t rowg = ((size_t)t*NN + node_g)*64;
                #pragma unroll
                for (int u = 0; u < 4; u++) {
                    float other = __shfl_xor_sync(0xffffffffu, of[u], 1);
                    float v0 = (lane & 1) ? other : of[u];
                    float v1 = (lane & 1) ? of[u] : other;
                    uint32_t h, l; split_pack(v0, v1, h, l);
                    int p = (lane >> 1) + 16*u;
                    if (lane & 1) g_attnL[rowg + p] = l;
                    else          g_attnH[rowg + p] = h;
                }
            }
        }

        // ---- commit prefetched A into the other buffer ----
        if (havepf) {
            uint32_t* AhiN = (uint32_t*)(smc + SA_AHI + (cur^1)*ABUF);
            uint32_t* AloN = (uint32_t*)(smc + SA_AHI + (cur^1)*ABUF + 8704);
            #pragma unroll
            for (int j = 0; j < 8; j++) {
                int i = tid + j*256;
                int row = i >> 6, cp = i & 63;
                uint32_t h, l; split_pack(pf[j].x, pf[j].y, h, l);
                AhiN[row*68 + cp] = h;
                AloN[row*68 + cp] = l;
            }
        }
        __syncthreads();   // A[next] staged; C reads done
        cur ^= 1;
    }
}

// ---------------- out kernel: M=32, 2 CTAs/SM, cp.async A staging ----------------
// smem: fcBlo 34816 | resBlo 18432 | Ahi 8704 | Alo 8704 | Xhi 4608 | Xlo 4608
//       C 32*132*4=16896 | par 2064  => 98832 (2 CTAs/SM)
#define SO_FCBLO  0
#define SO_RESBLO 34816
#define SO_AHI    53248
#define SO_ALO    61952
#define SO_XHI    70656
#define SO_XLO    75264
#define SO_C      79872
#define SO_PAR    96768
#define SO_TOTAL  98832

__global__ __launch_bounds__(256, 2) void out_mma_kernel(const float* __restrict__ x,
        const float* __restrict__ fc_w, const float* __restrict__ fc_b,
        const float* __restrict__ res_w, const float* __restrict__ res_b,
        const float* __restrict__ ln_g, const float* __restrict__ ln_b,
        float* __restrict__ out)
{
    extern __shared__ char smc[];
    uint32_t smb = smem_u32(smc);
    uint32_t* Xhi  = (uint32_t*)(smc + SO_XHI);
    uint32_t* Xlo  = (uint32_t*)(smc + SO_XLO);
    uint32_t* fBlo = (uint32_t*)(smc + SO_FCBLO);
    uint32_t* rBlo = (uint32_t*)(smc + SO_RESBLO);
    float*    C    = (float*)(smc + SO_C);
    float*    par  = (float*)(smc + SO_PAR);

    int tid = threadIdx.x, warp = tid >> 5, lane = tid & 31;
    int g = lane >> 2, tc = lane & 3;
    int n0 = warp * 16;

    for (int i = tid; i < 128*64; i += 256) {
        int n = i >> 6, cp = i & 63;
        float2 w = *(const float2*)(fc_w + n*128 + cp*2);
        uint32_t h, l; split_pack(w.x, w.y, h, l);
        fBlo[n*68 + cp] = l;
    }
    for (int i = tid; i < 128*32; i += 256) {
        int n = i >> 5, cp = i & 31;
        float2 w = *(const float2*)(res_w + n*64 + cp*2);
        uint32_t h, l; split_pack(w.x, w.y, h, l);
        rBlo[n*36 + cp] = l;
    }
    if (tid < 128) {
        par[tid] = fc_b[tid]; par[128+tid] = res_b[tid];
        par[256+tid] = ln_g[tid]; par[384+tid] = ln_b[tid];
    }
    if (tid == 0) par[512] = g_alpha[0];

    uint32_t bf[2][8][2], br[2][4][2];
    #pragma unroll
    for (int nn = 0; nn < 2; nn++) {
        int n = n0 + nn*8 + g;
        #pragma unroll
        for (int kk = 0; kk < 8; kk++) {
            int k = kk*16 + tc*2;
            float2 w0 = *(const float2*)(fc_w + n*128 + k);
            float2 w1 = *(const float2*)(fc_w + n*128 + k + 8);
            uint32_t h, l;
            split_pack(w0.x, w0.y, h, l); bf[nn][kk][0] = h;
            split_pack(w1.x, w1.y, h, l); bf[nn][kk][1] = h;
        }
        #pragma unroll
        for (int kk = 0; kk < 4; kk++) {
            int k = kk*16 + tc*2;
            float2 w0 = *(const float2*)(res_w + n*64 + k);
            float2 w1 = *(const float2*)(res_w + n*64 + k + 8);
            uint32_t h, l;
            split_pack(w0.x, w0.y, h, l); br[nn][kk][0] = h;
            split_pack(w1.x, w1.y, h, l); br[nn][kk][1] = h;
        }
    }
    float alpha_dummy = 0.f; (void)alpha_dummy;

    // ---- prologue: stage first tile (X conventional, A via cp.async) ----
    {
        int tile0 = blockIdx.x;
        size_t r0 = (size_t)tile0 * 32;
        for (int i = tid; i < 1024; i += 256) {
            int row = i >> 5, cp = i & 31;
            float2 a = *(const float2*)(x + (r0 + row)*HIN + cp*2);
            uint32_t h, l; split_pack(a.x, a.y, h, l);
            Xhi[row*36 + cp] = h; Xlo[row*36 + cp] = l;
        }
        const uint32_t* srcH = g_attnH + r0*64;
        const uint32_t* srcL = g_attnL + r0*64;
        for (int c = tid; c < 512; c += 256) {
            int row = c >> 4, off = c & 15;
            CP16(smb + SO_AHI + row*272 + off*16, srcH + row*64 + off*4);
            CP16(smb + SO_ALO + row*272 + off*16, srcL + row*64 + off*4);
        }
        CP_COMMIT();
    }
    CP_WAIT0();
    __syncthreads();
    float alpha = par[512];
    float beta  = 1.f - alpha;

    uint32_t aBaseHi = smb + SO_AHI + (uint32_t)(lane & 15)*272 + (uint32_t)(lane >> 4)*16;
    uint32_t aBaseLo = aBaseHi + (SO_ALO - SO_AHI);
    uint32_t xBaseHi = smb + SO_XHI + (uint32_t)(lane & 15)*144 + (uint32_t)(lane >> 4)*16;
    uint32_t xBaseLo = xBaseHi + (SO_XLO - SO_XHI);
    uint32_t bfBase[2], brBase[2];
    #pragma unroll
    for (int nn = 0; nn < 2; nn++) {
        bfBase[nn] = smb + SO_FCBLO  + (uint32_t)(n0 + nn*8 + (lane & 7))*272 + (uint32_t)((lane >> 3) & 1)*16;
        brBase[nn] = smb + SO_RESBLO + (uint32_t)(n0 + nn*8 + (lane & 7))*144 + (uint32_t)((lane >> 3) & 1)*16;
    }

    const int nTiles = (TT*NN)/32;   // 25000
    for (int tile = blockIdx.x; tile < nTiles; tile += gridDim.x) {
        int ptile = tile + gridDim.x;
        bool havepf = ptile < nTiles;
        // prefetch next tile's x rows into registers (hidden by MMA phase)
        float2 xf[4];
        if (havepf) {
            size_t r0n = (size_t)ptile * 32;
            #pragma unroll
            for (int j = 0; j < 4; j++) {
                int i = tid + j*256;
                int row = i >> 5, cp = i & 31;
                xf[j] = *(const float2*)(x + (r0n + row)*HIN + cp*2);
            }
        }

        // ---- MMA phase (reads A/X smem, writes C) ----
        #pragma unroll
        for (int mm = 0; mm < 2; mm++) {
            float accf[2][4];
            #pragma unroll
            for (int nn = 0; nn < 2; nn++) { accf[nn][0]=0.f; accf[nn][1]=0.f; accf[nn][2]=0.f; accf[nn][3]=0.f; }
            float accr[2][4];
            #pragma unroll
            for (int nn = 0; nn < 2; nn++) { accr[nn][0]=0.f; accr[nn][1]=0.f; accr[nn][2]=0.f; accr[nn][3]=0.f; }
            uint32_t aH = aBaseHi + (uint32_t)mm*4352;
            uint32_t aL = aBaseLo + (uint32_t)mm*4352;
            #pragma unroll
            for (int kh = 0; kh < 2; kh++) {
                #pragma unroll
                for (int q = 0; q < 4; q++) {
                    int kk = kh*4 + q;
                    uint32_t blf[2][2];
                    #pragma unroll
                    for (int nn = 0; nn < 2; nn++) ldsm_x2(blf[nn], bfBase[nn] + kk*32);
                    uint32_t ah[4], al[4];
                    ldsm_x4(ah, aH + kh*128 + q*32);
                    ldsm_x4(al, aL + kh*128 + q*32);
                    #pragma unroll
                    for (int nn = 0; nn < 2; nn++) mma16816(accf[nn], ah, bf[nn][kk]);
                    #pragma unroll
                    for (int nn = 0; nn < 2; nn++) mma16816(accf[nn], ah, blf[nn]);
                    #pragma unroll
                    for (int nn = 0; nn < 2; nn++) mma16816(accf[nn], al, bf[nn][kk]);
                }
            }
            {
                uint32_t xH = xBaseHi + (uint32_t)mm*2304;
                uint32_t xL = xBaseLo + (uint32_t)mm*2304;
                #pragma unroll
                for (int kk = 0; kk < 4; kk++) {
                    uint32_t blr[2][2];
                    #pragma unroll
                    for (int nn = 0; nn < 2; nn++) ldsm_x2(blr[nn], brBase[nn] + kk*32);
                    uint32_t ah[4], al[4];
                    ldsm_x4(ah, xH + kk*32);
                    ldsm_x4(al, xL + kk*32);
                    #pragma unroll
                    for (int nn = 0; nn < 2; nn++) mma16816(accr[nn], ah, br[nn][kk]);
                    #pragma unroll
                    for (int nn = 0; nn < 2; nn++) mma16816(accr[nn], ah, blr[nn]);
                    #pragma unroll
                    for (int nn = 0; nn < 2; nn++) mma16816(accr[nn], al, br[nn][kk]);
                }
            }
            #pragma unroll
            for (int nn = 0; nn < 2; nn++) {
                int j = n0 + nn*8 + tc*2;
                float2 fb = *(const float2*)(par + j);
                float2 rb = *(const float2*)(par + 128 + j);
                int rlo = mm*16 + g, rhi = rlo + 8;
                float v0 = fmaxf(accf[nn][0]+fb.x, 0.f)*alpha + (accr[nn][0]+rb.x)*beta;
                float v1 = fmaxf(accf[nn][1]+fb.y, 0.f)*alpha + (accr[nn][1]+rb.y)*beta;
                float v2 = fmaxf(accf[nn][2]+fb.x, 0.f)*alpha + (accr[nn][2]+rb.x)*beta;
                float v3 = fmaxf(accf[nn][3]+fb.y, 0.f)*alpha + (accr[nn][3]+rb.y)*beta;
                *(float2*)(C + rlo*132 + j) = make_float2(v0, v1);
                *(float2*)(C + rhi*132 + j) = make_float2(v2, v3);
            }
        }
        __syncthreads();   // C visible; A/X dead

        // ---- stage next tile: commit X regs, issue cp.async for A ----
        if (havepf) {
            #pragma unroll
            for (int j = 0; j < 4; j++) {
                int i = tid + j*256;
                int row = i >> 5, cp = i & 31;
                uint32_t h, l; split_pack(xf[j].x, xf[j].y, h, l);
                Xhi[row*36 + cp] = h; Xlo[row*36 + cp] = l;
            }
            size_t r0n = (size_t)ptile * 32;
            const uint32_t* srcH = g_attnH + r0n*64;
            const uint32_t* srcL = g_attnL + r0n*64;
            for (int c = tid; c < 512; c += 256) {
                int row = c >> 4, off = c & 15;
                CP16(smb + SO_AHI + row*272 + off*16, srcH + row*64 + off*4);
                CP16(smb + SO_ALO + row*272 + off*16, srcL + row*64 + off*4);
            }
            CP_COMMIT();
        }

        // ---- LayerNorm epilogue (overlaps cp.async) ----
        size_t r0 = (size_t)tile * 32;
        #pragma unroll
        for (int r8 = 0; r8 < 4; r8++) {
            int r = warp*4 + r8;
            float o[4];
            float s = 0.f, s2 = 0.f;
            #pragma unroll
            for (int u = 0; u < 4; u++) {
                o[u] = C[r*132 + lane + 32*u];
                s += o[u]; s2 += o[u]*o[u];
            }
            #pragma unroll
            for (int off = 16; off > 0; off >>= 1) {
                s  += __shfl_xor_sync(0xffffffffu, s,  off);
                s2 += __shfl_xor_sync(0xffffffffu, s2, off);
            }
            float mean = s * (1.f/HH);
            float var  = s2 * (1.f/HH) - mean*mean;
            float inv  = rsqrtf(var + 1e-5f);
            #pragma unroll
            for (int u = 0; u < 4; u++) {
                int col = lane + 32*u;
                out[(r0 + r)*HH + col] = (o[u]-mean)*inv*par[256+col] + par[384+col];
            }
        }
        CP_WAIT0();
        __syncthreads();   // A/X[next] ready; C reads done
    }
}

// ---------------- launch ----------------
extern "C" void kernel_launch(void* const* d_in, const int* in_sizes, int n_in,
                              void* d_out, int out_size)
{
    const float* inter     = (const float*)d_in[0];
    const float* x         = (const float*)d_in[1];
    const float* proj_w    = (const float*)d_in[2];
    const float* proj_b    = (const float*)d_in[3];
    const float* q_w       = (const float*)d_in[4];
    const float* k_w       = (const float*)d_in[5];
    const float* v_w       = (const float*)d_in[6];
    const float* fc_w      = (const float*)d_in[7];
    const float* fc_b      = (const float*)d_in[8];
    const float* res_w     = (const float*)d_in[9];
    const float* res_b     = (const float*)d_in[10];
    const float* res_alpha = (const float*)d_in[11];
    const float* ln_g      = (const float*)d_in[12];
    const float* ln_b      = (const float*)d_in[13];
    float* out = (float*)d_out;

    cudaFuncSetAttribute(attn_mma_kernel, cudaFuncAttributeMaxDynamicSharedMemorySize, SA_TOTAL);
    cudaFuncSetAttribute(out_mma_kernel,  cudaFuncAttributeMaxDynamicSharedMemorySize, SO_TOTAL);

    prep1_kernel<<<4, 256>>>(res_alpha);
    prep2_kernel<<<205, 256>>>(proj_w, proj_b, q_w, k_w, v_w);
    attn_mma_kernel<<<148, 256, SA_TOTAL>>>(inter);
    out_mma_kernel<<<296, 256, SO_TOTAL>>>(x, fc_w, fc_b, res_w, res_b, ln_g, ln_b, out);
}